// round 17
// baseline (speedup 1.0000x reference)
#include <cuda_runtime.h>
#include <cuda_bf16.h>
#include <math.h>

// NetVLAD: N=32, D=512, S=1600, K=64.
// d_in[0]=x [N,D,S] f32, d_in[1]=W [K,D] f32, d_in[2]=centroids [K,D] f32
// out: [N, K*D] f32

#define NN 32
#define DDIM 512
#define SDIM 1600
#define KK 64
#define NTILES 25   // s-tiles of 64

typedef __nv_bfloat16 bh;

__device__ __align__(16) bh g_wb[KK * DDIM];              // W bf16
__device__ __align__(16) float g_agg[NN * KK * DDIM];     // agg (atomic accum)
__device__ __align__(16) float g_asum_part[NN * NTILES * KK];

// smem layout (bytes) for the fused kernel
#define XS_PITCH 144
#define WOFF  73728            // Xs: 512*144
#define LOFF  83968            // W dbl-buf 2*5120 (As aliases after GEMM1)
#define R1OFF 100608           // Lsh 64*65*4 = 16640
#define R2OFF 102656           // red1 2048
#define SCOFF 103680           // red2 1024
#define SIOFF 103936           // sscale 256 | sinv 256
#define SMEM_TOTAL 104192

__device__ __forceinline__ unsigned packbf(float lo, float hi) {
    __nv_bfloat162 h = __floats2bfloat162_rn(lo, hi);
    return *(unsigned*)&h;
}

__device__ __forceinline__ void mma_bf16(float* c, unsigned a0, unsigned a1,
                                         unsigned a2, unsigned a3,
                                         unsigned b0, unsigned b1) {
    asm volatile(
        "mma.sync.aligned.m16n8k16.row.col.f32.bf16.bf16.f32 "
        "{%0,%1,%2,%3},{%4,%5,%6,%7},{%8,%9},{%0,%1,%2,%3};\n"
        : "+f"(c[0]), "+f"(c[1]), "+f"(c[2]), "+f"(c[3])
        : "r"(a0), "r"(a1), "r"(a2), "r"(a3), "r"(b0), "r"(b1));
}

__device__ __forceinline__ void cpa16(unsigned dst, const void* src) {
    asm volatile("cp.async.ca.shared.global [%0], [%1], 16;\n"
                 :: "r"(dst), "l"(src));
}
__device__ __forceinline__ void cp_commit() {
    asm volatile("cp.async.commit_group;\n");
}
template <int N> __device__ __forceinline__ void cp_wait() {
    asm volatile("cp.async.wait_group %0;\n" :: "n"(N));
}
__device__ __forceinline__ void ldsm4(unsigned& r0, unsigned& r1, unsigned& r2,
                                      unsigned& r3, unsigned a) {
    asm volatile("ldmatrix.sync.aligned.m8n8.x4.shared.b16 {%0,%1,%2,%3},[%4];\n"
                 : "=r"(r0), "=r"(r1), "=r"(r2), "=r"(r3) : "r"(a));
}
__device__ __forceinline__ void ldsm4t(unsigned& r0, unsigned& r1, unsigned& r2,
                                       unsigned& r3, unsigned a) {
    asm volatile("ldmatrix.sync.aligned.m8n8.x4.trans.shared.b16 {%0,%1,%2,%3},[%4];\n"
                 : "=r"(r0), "=r"(r1), "=r"(r2), "=r"(r3) : "r"(a));
}

// ---------------------------------------------------------------------------
// k_prepw: W -> bf16.
// ---------------------------------------------------------------------------
__global__ __launch_bounds__(256) void k_prepw(const float* __restrict__ W) {
    int i = blockIdx.x * 256 + threadIdx.x;
    g_wb[i] = __float2bfloat16(W[i]);
}

// ---------------------------------------------------------------------------
// k_zero: reset g_agg (graph replays re-run the whole pipeline).
// ---------------------------------------------------------------------------
__global__ __launch_bounds__(256) void k_zero() {
    int i = blockIdx.x * 256 + threadIdx.x;   // 1024 blocks: 262144 float4
    ((float4*)g_agg)[i] = make_float4(0.f, 0.f, 0.f, 0.f);
}

// ---------------------------------------------------------------------------
// k_fused: per (s-tile, n) CTA:
//   GEMM1: logits = W[64,512] @ x[512,64s]  (x retained in 72KB smem, bf16)
//   softmax over k (scaled by per-pixel invn), a_sum partial
//   a' = softmax*invn -> smem
//   GEMM2: agg_c[d,k] = sum_s x[d,s]*a'[k,s]  (all-smem) -> atomicAdd g_agg
// grid (25, 32), 256 thr = 8 warps.
// GEMM1 warp w: k-rows [(w>>1)*16,+16), s-cols [(w&1)*32,+32).
// GEMM2 half h (d 256h..256h+255), warp w: d-rows [256h+(w>>1)*64,+64),
//   k-cols [(w&1)*32,+32).
// ---------------------------------------------------------------------------
__global__ __launch_bounds__(256, 2) void k_fused(const float* __restrict__ x) {
    const int n = blockIdx.y;
    const int s0 = blockIdx.x * 64;
    const int tid = threadIdx.x;
    const int warp = tid >> 5, lane = tid & 31;
    const int gid = lane >> 2, tig = lane & 3;
    const int k0 = (warp >> 1) * 16;
    const int sh = (warp & 1) * 32;

    extern __shared__ __align__(16) char sm[];
    const unsigned smb = (unsigned)__cvta_generic_to_shared(sm);

    const float* xb = x + (size_t)n * DDIM * SDIM + s0;
    const int wk = tid >> 2, wc = (tid & 3) * 8;    // W: row wk, 8 bf16
    const int xd = tid >> 3, xs8 = (tid & 7) * 8;   // X: d-row xd, 8 s

    float acc[4][4];
#pragma unroll
    for (int j = 0; j < 4; j++)
#pragma unroll
        for (int i = 0; i < 4; i++) acc[j][i] = 0.f;
    float ss[8];
#pragma unroll
    for (int i = 0; i < 8; i++) ss[i] = 0.f;

    // ---- prologue: stage chunk 0 (x rows 0..31 + W buf 0) ----
    cpa16(smb + WOFF + wk * 80 + (tid & 3) * 16, g_wb + wk * DDIM + wc);
    cp_commit();
    {
        const float* xr = &xb[(size_t)xd * SDIM + xs8];
        float4 x0 = *(const float4*)xr;
        float4 x1 = *(const float4*)(xr + 4);
        ss[0] += x0.x * x0.x; ss[1] += x0.y * x0.y;
        ss[2] += x0.z * x0.z; ss[3] += x0.w * x0.w;
        ss[4] += x1.x * x1.x; ss[5] += x1.y * x1.y;
        ss[6] += x1.z * x1.z; ss[7] += x1.w * x1.w;
        uint4 xp = make_uint4(packbf(x0.x, x0.y), packbf(x0.z, x0.w),
                              packbf(x1.x, x1.y), packbf(x1.z, x1.w));
        *(uint4*)(sm + xd * XS_PITCH + xs8 * 2) = xp;
    }
    cp_wait<0>();
    __syncthreads();

    const int q = lane >> 3, rr = lane & 7;
    const int offA = (k0 + (q & 1) * 8 + rr) * 80 + (q >> 1) * 16;
    const int offBx = ((q & 1) * 8 + rr) * XS_PITCH + (q >> 1) * 16;

    // ---- GEMM1 mainloop: 16 d-chunks, x retained in Xs ----
#pragma unroll 2
    for (int c = 0; c < 16; c++) {
        const unsigned Wb = smb + WOFF + (c & 1) * 5120;
        const unsigned Xb = smb + (c * 32) * XS_PITCH;

        float4 nx0, nx1;
        if (c < 15) {
            const int dc = (c + 1) * 32;
            cpa16(smb + WOFF + ((c + 1) & 1) * 5120 + wk * 80 + (tid & 3) * 16,
                  g_wb + wk * DDIM + dc + wc);
            cp_commit();
            const float* xr = &xb[(size_t)(dc + xd) * SDIM + xs8];
            nx0 = *(const float4*)xr;
            nx1 = *(const float4*)(xr + 4);
        }

#pragma unroll
        for (int kk2 = 0; kk2 < 16; kk2 += 8) {   // d-offset = 2*kk2
            unsigned a0, a1, a2, a3;
            ldsm4(a0, a1, a2, a3, Wb + offA + kk2 * 4);
#pragma unroll
            for (int np = 0; np < 2; np++) {
                unsigned b0, b1, b2, b3;
                ldsm4t(b0, b1, b2, b3,
                       Xb + offBx + (kk2 * 2) * XS_PITCH + (sh + np * 16) * 2);
                mma_bf16(acc[np * 2],     a0, a1, a2, a3, b0, b1);
                mma_bf16(acc[np * 2 + 1], a0, a1, a2, a3, b2, b3);
            }
        }

        if (c < 15) {
            const int dc = (c + 1) * 32;
            ss[0] += nx0.x * nx0.x; ss[1] += nx0.y * nx0.y;
            ss[2] += nx0.z * nx0.z; ss[3] += nx0.w * nx0.w;
            ss[4] += nx1.x * nx1.x; ss[5] += nx1.y * nx1.y;
            ss[6] += nx1.z * nx1.z; ss[7] += nx1.w * nx1.w;
            uint4 xp = make_uint4(packbf(nx0.x, nx0.y), packbf(nx0.z, nx0.w),
                                  packbf(nx1.x, nx1.y), packbf(nx1.z, nx1.w));
            *(uint4*)(sm + (dc + xd) * XS_PITCH + xs8 * 2) = xp;
        }
        cp_wait<0>();
        __syncthreads();
    }

    // ---- softmax epilogue ----
    float (*Lsh)[65] = (float(*)[65])(sm + LOFF);
    float* red1   = (float*)(sm + R1OFF);   // [8][64]
    float* red2   = (float*)(sm + R2OFF);   // [4][64]
    float* sscale = (float*)(sm + SCOFF);
    float* sinv   = (float*)(sm + SIOFF);

#pragma unroll
    for (int j = 0; j < 4; j++) {
        Lsh[k0 + gid][sh + j * 8 + 2 * tig]         = acc[j][0];
        Lsh[k0 + gid][sh + j * 8 + 2 * tig + 1]     = acc[j][1];
        Lsh[k0 + gid + 8][sh + j * 8 + 2 * tig]     = acc[j][2];
        Lsh[k0 + gid + 8][sh + j * 8 + 2 * tig + 1] = acc[j][3];
    }
    {   // sumsq: fold 4 d-row groups per warp, then [8 warps][64 s] partials
        float v[8];
#pragma unroll
        for (int i = 0; i < 8; i++) v[i] = ss[i];
#pragma unroll
        for (int i = 0; i < 8; i++) {
            v[i] += __shfl_xor_sync(0xffffffffu, v[i], 8);
            v[i] += __shfl_xor_sync(0xffffffffu, v[i], 16);
        }
        if (lane < 8) {
#pragma unroll
            for (int i = 0; i < 8; i++)
                red1[warp * 64 + lane * 8 + i] = v[i];
        }
    }
    __syncthreads();
    const int qq = tid >> 6, s = tid & 63;
    float tot = 0.f;
#pragma unroll
    for (int w = 0; w < 8; w++) tot += red1[w * 64 + s];
    const float sc = 1.f / fmaxf(sqrtf(tot), 1e-12f);
    __syncthreads();

    float m = -1e30f;
#pragma unroll
    for (int kq = 0; kq < 16; kq++) m = fmaxf(m, Lsh[qq * 16 + kq][s] * sc);
    red1[qq * 64 + s] = m;
    __syncthreads();
    m = fmaxf(fmaxf(red1[s], red1[64 + s]), fmaxf(red1[128 + s], red1[192 + s]));

    float sump = 0.f;
#pragma unroll
    for (int kq = 0; kq < 16; kq++) {
        float e = __expf(Lsh[qq * 16 + kq][s] * sc - m);
        Lsh[qq * 16 + kq][s] = e;
        sump += e;
    }
    red2[qq * 64 + s] = sump;
    if (qq == 0) sscale[s] = sc;
    __syncthreads();
    if (qq == 0) {
        float sum = red2[s] + red2[64 + s] + red2[128 + s] + red2[192 + s];
        sinv[s] = 1.f / sum;
    }
    __syncthreads();

    {   // a_sum partial: 4 threads per k
        const int k = tid & 63;
        float t = 0.f;
#pragma unroll
        for (int sq = 0; sq < 16; sq++) {
            int sp = qq * 16 + sq;
            t += Lsh[k][sp] * sinv[sp];
        }
        red1[qq * 64 + k] = t;
    }
    __syncthreads();
    if (tid < 64)
        g_asum_part[((size_t)n * NTILES + blockIdx.x) * KK + tid] =
            red1[tid] + red1[64 + tid] + red1[128 + tid] + red1[192 + tid];

    // a' = softmax*invn -> bf16 into smem As (aliases W buffers; W is done)
#pragma unroll
    for (int i = 0; i < 8; i++) {
        int idx = tid + i * 256;
        int k = idx >> 5, s2 = (idx & 31) * 2;
        float v0 = Lsh[k][s2] * sinv[s2] * sscale[s2];
        float v1 = Lsh[k][s2 + 1] * sinv[s2 + 1] * sscale[s2 + 1];
        *(unsigned*)(sm + WOFF + k * XS_PITCH + s2 * 2) = packbf(v0, v1);
    }
    __syncthreads();

    // ---- GEMM2 (all-smem): agg_c[d,k] = sum_s x[d,s]*a'[k,s] ----
    const unsigned AsB = smb + WOFF;
    const int kh2 = (warp & 1) * 32;
    const int offB2 = (kh2 + q * 8 + rr) * XS_PITCH;
    const int offA2 = ((q & 1) * 8 + rr) * XS_PITCH + (q >> 1) * 16;
    float* aggb = g_agg + (size_t)n * KK * DDIM;

#pragma unroll 1
    for (int h = 0; h < 2; h++) {
        const int d0 = h * 256 + (warp >> 1) * 64;
        float acc2[4][4][4];
#pragma unroll
        for (int mf = 0; mf < 4; mf++)
#pragma unroll
            for (int nf = 0; nf < 4; nf++)
#pragma unroll
                for (int e = 0; e < 4; e++) acc2[mf][nf][e] = 0.f;

#pragma unroll
        for (int st = 0; st < 4; st++) {      // s-steps of 16
            unsigned p0, p1, p2, p3, h0, h1, h2, h3;
            ldsm4(p0, p1, p2, p3, AsB + offB2 + st * 32);        // s lo
            ldsm4(h0, h1, h2, h3, AsB + offB2 + st * 32 + 16);   // s hi
#pragma unroll
            for (int mf = 0; mf < 4; mf++) {
                unsigned a0, a1, a2, a3;
                ldsm4(a0, a1, a2, a3,
                      smb + (d0 + mf * 16) * XS_PITCH + offA2 + st * 32);
                mma_bf16(acc2[mf][0], a0, a1, a2, a3, p0, h0);
                mma_bf16(acc2[mf][1], a0, a1, a2, a3, p1, h1);
                mma_bf16(acc2[mf][2], a0, a1, a2, a3, p2, h2);
                mma_bf16(acc2[mf][3], a0, a1, a2, a3, p3, h3);
            }
        }

        // atomic accumulate: element (d = d0+mf*16+gid(+8), k = kh2+nf*8+2tig(+1))
#pragma unroll
        for (int mf = 0; mf < 4; mf++) {
            const int d = d0 + mf * 16 + gid;
#pragma unroll
            for (int nf = 0; nf < 4; nf++) {
                const int k = kh2 + nf * 8 + 2 * tig;
                atomicAdd(aggb + (size_t)k * DDIM + d,           acc2[mf][nf][0]);
                atomicAdd(aggb + (size_t)(k + 1) * DDIM + d,     acc2[mf][nf][1]);
                atomicAdd(aggb + (size_t)k * DDIM + d + 8,       acc2[mf][nf][2]);
                atomicAdd(aggb + (size_t)(k + 1) * DDIM + d + 8, acc2[mf][nf][3]);
            }
        }
    }
}

// ---------------------------------------------------------------------------
// k_final: a_sum reduce; vlad = agg - a_sum*c; intra-norm; *1/8
// (global norm of 64 unit rows is exactly 8). grid (64,32), 128 thr.
// ---------------------------------------------------------------------------
__global__ __launch_bounds__(128) void k_final(const float* __restrict__ cent,
                                               float* __restrict__ out) {
    const int k = blockIdx.x, n = blockIdx.y;
    const int tid = threadIdx.x;

    __shared__ float s_as;
    __shared__ float wpart[4];

    if (tid < 32) {
        float p = (tid < NTILES)
                      ? g_asum_part[((size_t)n * NTILES + tid) * KK + k]
                      : 0.f;
#pragma unroll
        for (int o = 16; o > 0; o >>= 1) p += __shfl_xor_sync(0xffffffffu, p, o);
        if (tid == 0) s_as = p;
    }
    __syncthreads();
    const float as = s_as;

    float4 ag = *(const float4*)&g_agg[((size_t)n * KK + k) * DDIM + tid * 4];
    float4 c4 = *(const float4*)&cent[(size_t)k * DDIM + tid * 4];
    float vx = ag.x - as * c4.x;
    float vy = ag.y - as * c4.y;
    float vz = ag.z - as * c4.z;
    float vw = ag.w - as * c4.w;
    float ss = vx * vx + vy * vy + vz * vz + vw * vw;

#pragma unroll
    for (int o = 16; o > 0; o >>= 1) ss += __shfl_xor_sync(0xffffffffu, ss, o);
    if ((tid & 31) == 0) wpart[tid >> 5] = ss;
    __syncthreads();
    float tot = wpart[0] + wpart[1] + wpart[2] + wpart[3];

    const float inv = 0.125f / fmaxf(sqrtf(tot), 1e-12f);
    float4 o4 = make_float4(vx * inv, vy * inv, vz * inv, vw * inv);
    *(float4*)&out[(size_t)n * (KK * DDIM) + (size_t)k * DDIM + tid * 4] = o4;
}

extern "C" void kernel_launch(void* const* d_in, const int* in_sizes, int n_in,
                              void* d_out, int out_size) {
    const float* x    = (const float*)d_in[0];
    const float* W    = (const float*)d_in[1];
    const float* cent = (const float*)d_in[2];
    float* out = (float*)d_out;

    cudaFuncSetAttribute(k_fused, cudaFuncAttributeMaxDynamicSharedMemorySize,
                         SMEM_TOTAL);

    k_prepw<<<128, 256>>>(W);
    k_zero<<<1024, 256>>>();
    k_fused<<<dim3(NTILES, NN), 256, SMEM_TOTAL>>>(x);
    k_final<<<dim3(KK, NN), 128>>>(cent, out);
}